// round 1
// baseline (speedup 1.0000x reference)
#include <cuda_runtime.h>
#include <cuda_bf16.h>
#include <math.h>

#define BATCH 2048
#define IN_C  256
#define OUT_C 256
#define NSPL  5
#define NINT  16

#define BM 64   // batch tile
#define BO 32   // out tile
#define IC 32   // i-chunk

// Precomputed, constant-folded spline parameters, transposed to [k][i][o]
// k: 0=b3*log2e, 1=b4, 2=b2*ln2, 3=b1*g*ln2, 4=b5*g   (g = softplus(raw_gamma)/256)
__device__ float g_par[5][IN_C * OUT_C];

__device__ __forceinline__ float ex2f(float x) {
    float r; asm("ex2.approx.f32 %0, %1;" : "=f"(r) : "f"(x)); return r;
}
__device__ __forceinline__ float lg2f(float x) {
    float r; asm("lg2.approx.f32 %0, %1;" : "=f"(r) : "f"(x)); return r;
}

__global__ void kan_precompute(const float* __restrict__ w,
                               const float* __restrict__ raw_gamma,
                               const float* __restrict__ breaks,
                               const float* __restrict__ coefs,
                               const float* __restrict__ mu_p,
                               const float* __restrict__ sigma_p) {
    int idx = blockIdx.x * blockDim.x + threadIdx.x;
    if (idx >= OUT_C * IN_C) return;
    int o = idx / IN_C;
    int i = idx - o * IN_C;

    float mu = *mu_p;
    float sigma = *sigma_p;

    float wv = w[idx];
    wv = fminf(fmaxf(wv, 5.5f), 35.5f);
    float wn = (wv - mu) / sigma;

    float b[NSPL];
#pragma unroll
    for (int s = 0; s < NSPL; s++) {
        const float* brk = breaks + s * (NINT + 1);
        float lo = brk[0];
        float hib = brk[NINT] - 1e-6f;
        float wc = fminf(fmaxf(wn, lo), hib);
        // searchsorted(breaks, wc, 'right') - 1, clipped to [0, NINT-1]
        int k = 0;
#pragma unroll
        for (int kk = 1; kk <= NINT; kk++) k += (brk[kk] <= wc) ? 1 : 0;
        if (k > NINT - 1) k = NINT - 1;
        float t = wc - brk[k];
        const float* a = coefs + (s * NINT + k) * 4;
        b[s] = ((a[0] * t + a[1]) * t + a[2]) * t + a[3];
    }

    // gamma = softplus(raw_gamma) ; scale by 1/OUT_C
    float rg = raw_gamma[idx];
    float g = fmaxf(rg, 0.0f) + log1pf(expf(-fabsf(rg)));
    g *= (1.0f / (float)OUT_C);

    const float LN2 = 0.69314718055994530942f;
    const float L2E = 1.44269504088896340736f;

    int tix = i * OUT_C + o;  // transposed layout [i][o]
    g_par[0][tix] = b[2] * L2E;      // b3'
    g_par[1][tix] = b[3];            // b4
    g_par[2][tix] = b[1] * LN2;      // b2'
    g_par[3][tix] = b[0] * g * LN2;  // c1'
    g_par[4][tix] = b[4] * g;        // c5'
}

__global__ void __launch_bounds__(256)
kan_main(const float* __restrict__ x, float* __restrict__ out) {
    __shared__ float x_s[BM][IC];
    __shared__ float p_s[5][IC][BO];

    int tid  = threadIdx.x;
    int lane = tid & 31;       // -> output o within tile
    int wrp  = tid >> 5;       // 0..7 -> batch subgroup
    int b0 = blockIdx.x * BM;
    int o0 = blockIdx.y * BO;

    float acc[8];
#pragma unroll
    for (int j = 0; j < 8; j++) acc[j] = 0.0f;

    for (int ic = 0; ic < IN_C; ic += IC) {
        __syncthreads();
        // load x tile (apply relu): 64 rows x 32 cols, coalesced
#pragma unroll
        for (int r = wrp; r < BM; r += 8) {
            float v = x[(b0 + r) * IN_C + ic + lane];
            x_s[r][lane] = fmaxf(v, 0.0f);
        }
        // load param tiles: [k][i][o], coalesced stride-1 in o
#pragma unroll
        for (int k = 0; k < 5; k++) {
#pragma unroll
            for (int r = wrp; r < IC; r += 8) {
                p_s[k][r][lane] = g_par[k][(ic + r) * OUT_C + o0 + lane];
            }
        }
        __syncthreads();

        int wb = wrp * 8;
        for (int ii = 0; ii < IC; ii++) {
            float b3p = p_s[0][ii][lane];
            float b4  = p_s[1][ii][lane];
            float b2p = p_s[2][ii][lane];
            float c1p = p_s[3][ii][lane];
            float c5g = p_s[4][ii][lane];
#pragma unroll
            for (int j = 0; j < 8; j++) {
                float xv = x_s[wb + j][ii];  // same across all lanes -> uniform branch
                if (xv > 0.0f) {
                    float e    = ex2f(b3p * xv);           // exp(b3*x)
                    float base = fmaxf(e - 1.0f, 0.0f);    // guard approx <1
                    float pw   = ex2f(b4 * lg2f(base));    // base^b4 (base=0 -> -inf -> 0)
                    float lgA  = lg2f(pw + 1.0f);          // log2(1+pw)
                    float lgB  = lg2f(fmaf(b2p, lgA, 1.0f)); // log2(1 + b2*ln2*lgA)
                    acc[j] = fmaf(c1p, lgB, acc[j]);
                    acc[j] = fmaf(c5g, xv, acc[j]);
                }
            }
        }
    }

    // epilogue: softplus + store (coalesced over o)
#pragma unroll
    for (int j = 0; j < 8; j++) {
        int b = b0 + wrp * 8 + j;
        float y = acc[j];
        float sp = fmaxf(y, 0.0f) + log1pf(expf(-fabsf(y)));
        out[b * OUT_C + o0 + lane] = sp;
    }
}

extern "C" void kernel_launch(void* const* d_in, const int* in_sizes, int n_in,
                              void* d_out, int out_size) {
    const float* x         = (const float*)d_in[0];
    const float* w         = (const float*)d_in[1];
    const float* raw_gamma = (const float*)d_in[2];
    const float* breaks    = (const float*)d_in[3];
    const float* coefs     = (const float*)d_in[4];
    const float* mu        = (const float*)d_in[5];
    const float* sigma     = (const float*)d_in[6];
    float* out = (float*)d_out;

    kan_precompute<<<(OUT_C * IN_C + 255) / 256, 256>>>(w, raw_gamma, breaks, coefs, mu, sigma);

    dim3 grid(BATCH / BM, OUT_C / BO);
    kan_main<<<grid, 256>>>(x, out);
}

// round 2
// speedup vs baseline: 1.6622x; 1.6622x over previous
#include <cuda_runtime.h>
#include <cuda_bf16.h>
#include <math.h>

#define BATCH 2048
#define IN_C  256
#define OUT_C 256
#define NSPL  5
#define NINT  16

#define IC     64              // i-chunk
#define NCHUNK (IN_C / IC)     // 4
#define BM     8               // batches per block (1 per warp)
#define BO     32              // outputs per block (1 per lane)

// Precomputed, constant-folded spline params, transposed to [k][i][o]
// k: 0=b3*log2e, 1=b4, 2=b2*ln2, 3=b1*g*ln2, 4=b5*g  (g = softplus(raw_gamma)/256)
__device__ float g_par[5][IN_C * OUT_C];
// Per-batch compacted active inputs: chunk c of batch b occupies [b*256 + c*64, +cnt)
__device__ float2 g_act[BATCH * IN_C];
__device__ int    g_cnt[BATCH * NCHUNK];

__device__ __forceinline__ float ex2f(float x) {
    float r; asm("ex2.approx.f32 %0, %1;" : "=f"(r) : "f"(x)); return r;
}
__device__ __forceinline__ float lg2f(float x) {
    float r; asm("lg2.approx.f32 %0, %1;" : "=f"(r) : "f"(x)); return r;
}

__global__ void kan_precompute(const float* __restrict__ w,
                               const float* __restrict__ raw_gamma,
                               const float* __restrict__ breaks,
                               const float* __restrict__ coefs,
                               const float* __restrict__ mu_p,
                               const float* __restrict__ sigma_p) {
    int idx = blockIdx.x * blockDim.x + threadIdx.x;
    if (idx >= OUT_C * IN_C) return;
    int o = idx / IN_C;
    int i = idx - o * IN_C;

    float mu = *mu_p;
    float sigma = *sigma_p;

    float wv = w[idx];
    wv = fminf(fmaxf(wv, 5.5f), 35.5f);
    float wn = (wv - mu) / sigma;

    float b[NSPL];
#pragma unroll
    for (int s = 0; s < NSPL; s++) {
        const float* brk = breaks + s * (NINT + 1);
        float lo = brk[0];
        float hib = brk[NINT] - 1e-6f;
        float wc = fminf(fmaxf(wn, lo), hib);
        int k = 0;
#pragma unroll
        for (int kk = 1; kk <= NINT; kk++) k += (brk[kk] <= wc) ? 1 : 0;
        if (k > NINT - 1) k = NINT - 1;
        float t = wc - brk[k];
        const float* a = coefs + (s * NINT + k) * 4;
        b[s] = ((a[0] * t + a[1]) * t + a[2]) * t + a[3];
    }

    float rg = raw_gamma[idx];
    float g = fmaxf(rg, 0.0f) + log1pf(expf(-fabsf(rg)));
    g *= (1.0f / (float)OUT_C);

    const float LN2 = 0.69314718055994530942f;
    const float L2E = 1.44269504088896340736f;

    int tix = i * OUT_C + o;
    g_par[0][tix] = b[2] * L2E;
    g_par[1][tix] = b[3];
    g_par[2][tix] = b[1] * LN2;
    g_par[3][tix] = b[0] * g * LN2;
    g_par[4][tix] = b[4] * g;
}

// Per-batch, per-chunk compaction of active (x>0) inputs. One warp per batch.
__global__ void kan_compact(const float* __restrict__ x) {
    int w = threadIdx.x >> 5, lane = threadIdx.x & 31;
    int b = blockIdx.x * BM + w;
    int base = b * IN_C;
#pragma unroll
    for (int c = 0; c < NCHUNK; c++) {
        int cbase = base + c * IC;
        int cnt = 0;
#pragma unroll
        for (int h = 0; h < IC / 32; h++) {
            int il = h * 32 + lane;
            float xv = x[cbase + il];
            bool act = xv > 0.0f;
            unsigned m = __ballot_sync(0xffffffffu, act);
            int pos = __popc(m & ((1u << lane) - 1));
            if (act) g_act[cbase + cnt + pos] = make_float2(xv, __int_as_float(il));
            cnt += __popc(m);
        }
        int padded = (cnt + 3) & ~3;
        if (lane < padded - cnt)
            g_act[cbase + cnt + lane] = make_float2(0.0f, __int_as_float(0));
        if (lane == 0) g_cnt[b * NCHUNK + c] = padded;
    }
}

__global__ void __launch_bounds__(256)
kan_main(float* __restrict__ out) {
    __shared__ float  p_s[5][IC][BO];
    __shared__ float2 act_s[BM][IC];
    __shared__ int    cnt_s[BM];

    int tid  = threadIdx.x;
    int lane = tid & 31;
    int w    = tid >> 5;
    int b    = blockIdx.x * BM + w;
    int o0   = blockIdx.y * BO;

    float acc = 0.0f;

#pragma unroll
    for (int c = 0; c < NCHUNK; c++) {
        __syncthreads();
        // stage params [5][IC][32], coalesced, conflict-free
#pragma unroll
        for (int k = 0; k < 5; k++)
#pragma unroll
            for (int r = w; r < IC; r += 8)
                p_s[k][r][lane] = g_par[k][(c * IC + r) * OUT_C + o0 + lane];
        // stage this warp's batch active list for the chunk
#pragma unroll
        for (int il = lane; il < IC; il += 32)
            act_s[w][il] = g_act[b * IN_C + c * IC + il];
        if (lane == 0) cnt_s[w] = g_cnt[b * NCHUNK + c];
        __syncthreads();

        int cnt = cnt_s[w];
        for (int n = 0; n < cnt; n += 4) {
            float2 ee[4];
#pragma unroll
            for (int q = 0; q < 4; q++) ee[q] = act_s[w][n + q];
#pragma unroll
            for (int q = 0; q < 4; q++) {
                float xv = ee[q].x;
                int   il = __float_as_int(ee[q].y);
                float b3p = p_s[0][il][lane];
                float b4  = p_s[1][il][lane];
                float b2p = p_s[2][il][lane];
                float c1p = p_s[3][il][lane];
                float c5g = p_s[4][il][lane];
                float e    = ex2f(b3p * xv);
                float base = fmaxf(e - 1.0f, 0.0f);
                float pw   = ex2f(b4 * lg2f(base));       // base^b4 (0 -> 0)
                float lgA  = lg2f(pw + 1.0f);
                float lgB  = lg2f(fmaf(b2p, lgA, 1.0f));
                acc = fmaf(c1p, lgB, fmaf(c5g, xv, acc));
            }
        }
    }

    float y  = acc;
    float sp = fmaxf(y, 0.0f) + log1pf(expf(-fabsf(y)));
    out[b * OUT_C + o0 + lane] = sp;
}

extern "C" void kernel_launch(void* const* d_in, const int* in_sizes, int n_in,
                              void* d_out, int out_size) {
    const float* x         = (const float*)d_in[0];
    const float* w         = (const float*)d_in[1];
    const float* raw_gamma = (const float*)d_in[2];
    const float* breaks    = (const float*)d_in[3];
    const float* coefs     = (const float*)d_in[4];
    const float* mu        = (const float*)d_in[5];
    const float* sigma     = (const float*)d_in[6];
    float* out = (float*)d_out;

    kan_precompute<<<(OUT_C * IN_C + 255) / 256, 256>>>(w, raw_gamma, breaks, coefs, mu, sigma);
    kan_compact<<<BATCH / BM, 256>>>(x);

    dim3 grid(BATCH / BM, OUT_C / BO);
    kan_main<<<grid, 256>>>(x ? out : out);
}

// round 4
// speedup vs baseline: 1.8690x; 1.1245x over previous
#include <cuda_runtime.h>
#include <cuda_bf16.h>
#include <math.h>

#define BATCH 2048
#define IN_C  256
#define OUT_C 256
#define NSPL  5
#define NINT  16

// params: float4 = {b3*log2e, b4, b2*ln2, b1*g*ln2}, scalar = b5*g, layout [i][o]
__device__ float4 g_par4[IN_C * OUT_C];
__device__ float  g_par1[IN_C * OUT_C];
// per-batch compacted active list: (x, i*256 as int bits), padded to multiple of 4
__device__ float2 g_act[BATCH * IN_C];
__device__ int    g_cnt[BATCH];

__device__ __forceinline__ float ex2f(float x) {
    float r; asm("ex2.approx.f32 %0, %1;" : "=f"(r) : "f"(x)); return r;
}
__device__ __forceinline__ float lg2f(float x) {
    float r; asm("lg2.approx.f32 %0, %1;" : "=f"(r) : "f"(x)); return r;
}

// Merged pre-pass: blocks [0,256) compute spline params; blocks [256,512) compact x.
__global__ void __launch_bounds__(256)
kan_pre(const float* __restrict__ x,
        const float* __restrict__ w,
        const float* __restrict__ raw_gamma,
        const float* __restrict__ breaks,
        const float* __restrict__ coefs,
        const float* __restrict__ mu_p,
        const float* __restrict__ sigma_p) {
    if (blockIdx.x < 256) {
        // ---- param precompute: thread -> (i = idx>>8, o = idx&255), writes coalesced
        __shared__ float brk_s[NSPL][NINT + 1];
        __shared__ float cf_s[NSPL * NINT * 4];
        int tid = threadIdx.x;
        for (int j = tid; j < NSPL * (NINT + 1); j += 256)
            brk_s[j / (NINT + 1)][j % (NINT + 1)] = breaks[j];
        for (int j = tid; j < NSPL * NINT * 4; j += 256)   // 320 elems: needs the loop!
            cf_s[j] = coefs[j];
        __syncthreads();

        int idx = blockIdx.x * 256 + tid;
        int i = idx >> 8;
        int o = idx & 255;
        int widx = o * IN_C + i;   // w is [OUT][IN]

        float mu = *mu_p, sigma = *sigma_p;
        float wv = w[widx];
        wv = fminf(fmaxf(wv, 5.5f), 35.5f);
        float wn = (wv - mu) / sigma;

        float b[NSPL];
#pragma unroll
        for (int s = 0; s < NSPL; s++) {
            float lo = brk_s[s][0];
            float hib = brk_s[s][NINT] - 1e-6f;
            float wc = fminf(fmaxf(wn, lo), hib);
            int k = 0;
#pragma unroll
            for (int kk = 1; kk <= NINT; kk++) k += (brk_s[s][kk] <= wc) ? 1 : 0;
            if (k > NINT - 1) k = NINT - 1;
            float t = wc - brk_s[s][k];
            const float* a = &cf_s[(s * NINT + k) * 4];
            b[s] = ((a[0] * t + a[1]) * t + a[2]) * t + a[3];
        }

        float rg = raw_gamma[widx];
        float g = fmaxf(rg, 0.0f) + log1pf(expf(-fabsf(rg)));
        g *= (1.0f / (float)OUT_C);

        const float LN2 = 0.69314718055994530942f;
        const float L2E = 1.44269504088896340736f;
        g_par4[idx] = make_float4(b[2] * L2E, b[3], b[1] * LN2, b[0] * g * LN2);
        g_par1[idx] = b[4] * g;
    } else {
        // ---- compaction: one warp per batch, full 256-i list
        int wrp = threadIdx.x >> 5, lane = threadIdx.x & 31;
        int b = (blockIdx.x - 256) * 8 + wrp;
        const float* xb = x + b * IN_C;
        int cnt = 0;
#pragma unroll
        for (int h = 0; h < IN_C / 32; h++) {
            int il = h * 32 + lane;
            float xv = xb[il];
            bool act = xv > 0.0f;
            unsigned m = __ballot_sync(0xffffffffu, act);
            int pos = __popc(m & ((1u << lane) - 1));
            if (act) g_act[b * IN_C + cnt + pos] =
                         make_float2(xv, __int_as_float(il << 8));  // i pre-scaled by 256
            cnt += __popc(m);
        }
        int padded = (cnt + 3) & ~3;
        if (lane < padded - cnt)
            g_act[b * IN_C + cnt + lane] = make_float2(0.0f, __int_as_float(0));
        if (lane == 0) g_cnt[b] = padded;
    }
}

__global__ void __launch_bounds__(256)
kan_main(float* __restrict__ out) {
    int tid  = threadIdx.x;
    int lane = tid & 31;
    int wrp  = tid >> 5;
    int b    = blockIdx.x * 8 + wrp;         // one batch per warp
    int o    = blockIdx.y * 32 + lane;       // one output per lane

    const float4* __restrict__ p4 = g_par4 + o;
    const float*  __restrict__ p1 = g_par1 + o;
    const float4* __restrict__ ap = (const float4*)(g_act + b * IN_C);

    int cnt = g_cnt[b];
    float acc0 = 0.0f, acc1 = 0.0f, acc2 = 0.0f, acc3 = 0.0f;

    for (int n = 0; n < cnt; n += 4) {
        float4 e01 = __ldg(&ap[n >> 1]);
        float4 e23 = __ldg(&ap[(n >> 1) + 1]);
        float xs[4] = {e01.x, e01.z, e23.x, e23.z};
        int   is[4] = {__float_as_int(e01.y), __float_as_int(e01.w),
                       __float_as_int(e23.y), __float_as_int(e23.w)};
        float4 P[4];
        float  c5[4];
#pragma unroll
        for (int q = 0; q < 4; q++) {
            P[q]  = __ldg(p4 + is[q]);
            c5[q] = __ldg(p1 + is[q]);
        }
        float r[4];
#pragma unroll
        for (int q = 0; q < 4; q++) {
            float xv   = xs[q];
            float e    = ex2f(P[q].x * xv);
            float base = fmaxf(e - 1.0f, 0.0f);
            float pw   = ex2f(P[q].y * lg2f(base));       // base^b4 (0 -> 0)
            float lgA  = lg2f(pw + 1.0f);
            float lgB  = lg2f(fmaf(P[q].z, lgA, 1.0f));
            r[q] = fmaf(P[q].w, lgB, c5[q] * xv);
        }
        acc0 += r[0]; acc1 += r[1]; acc2 += r[2]; acc3 += r[3];
    }

    float y  = (acc0 + acc1) + (acc2 + acc3);
    float sp = fmaxf(y, 0.0f) + log1pf(expf(-fabsf(y)));
    out[b * OUT_C + o] = sp;
}

extern "C" void kernel_launch(void* const* d_in, const int* in_sizes, int n_in,
                              void* d_out, int out_size) {
    const float* x         = (const float*)d_in[0];
    const float* w         = (const float*)d_in[1];
    const float* raw_gamma = (const float*)d_in[2];
    const float* breaks    = (const float*)d_in[3];
    const float* coefs     = (const float*)d_in[4];
    const float* mu        = (const float*)d_in[5];
    const float* sigma     = (const float*)d_in[6];
    float* out = (float*)d_out;

    kan_pre<<<512, 256>>>(x, w, raw_gamma, breaks, coefs, mu, sigma);

    dim3 grid(BATCH / 8, OUT_C / 32);
    kan_main<<<grid, 256>>>(out);
}